// round 3
// baseline (speedup 1.0000x reference)
#include <cuda_runtime.h>
#include <cstdint>
#include <cstddef>

// ============================================================================
// TT-Linear as two merged GEMMs, fp32 with packed f32x2 FFMA.
//
//   G01[(o1,o2,r2)][(i1,i2)] = sum_r1 core0[i1,o1,r1] * core1[r1,i2,o2,r2]
//   G23[(r2,i3,i4)][(o3,o4)] = sum_r3 core2[r2,i3,o3,r3] * core3[r3,i4,o4]
//
//   GEMM1: z1[b][(o12,r2)][(i34)] = G01 (512x64) @ x_b (64x64)
//   GEMM2: y[b][(o12)][(o34)]    = z1_b (64x512) @ G23 (512x64) + bias
//
// z1 flat layout b*32768 + (o12*8+r2)*64 + i34 == b*32768 + o12*512 + (r2*64+i34)
// serves both GEMMs without any transpose.
// ============================================================================

__device__ __align__(16) float g_AT[64 * 512];   // G01 transposed: [k=i12][m=(o1,o2,r2)]
__device__ __align__(16) float g_B2[512 * 64];   // G23:            [k=(r2,i3,i4)][n=(o3,o4)]
__device__ __align__(16) float g_z1[134217728];  // [b=4096][m=512][n=64]  (512 MiB scratch)

__device__ __forceinline__ unsigned long long pack2(float v) {
    unsigned long long r;
    asm("mov.b64 %0, {%1, %1};" : "=l"(r) : "f"(v));
    return r;
}
__device__ __forceinline__ void ffma2(unsigned long long& d,
                                      unsigned long long a,
                                      unsigned long long b) {
    // packed 2-lane fp32 fma: d.lo += a.lo*b.lo ; d.hi += a.hi*b.hi
    asm("fma.rn.f32x2 %0, %1, %2, %0;" : "+l"(d) : "l"(a), "l"(b));
}

union U2F { unsigned long long u; float2 f; };

// ---------------------------------------------------------------------------
// Merge the TT cores into G01^T and G23. 65536 entries, 8 MACs each.
// ---------------------------------------------------------------------------
__global__ void k_prep(const float* __restrict__ c0, const float* __restrict__ c1,
                       const float* __restrict__ c2, const float* __restrict__ c3) {
    int t = blockIdx.x * blockDim.x + threadIdx.x;  // 0..65535
    if (t < 32768) {
        // g_AT[k*512 + m], k=(i1,i2), m=(o1,o2,r2)
        int k = t >> 9, m = t & 511;
        int i1 = k >> 3, i2 = k & 7;
        int o1 = m >> 6, o2 = (m >> 3) & 7, r2 = m & 7;
        float s = 0.0f;
#pragma unroll
        for (int r1 = 0; r1 < 8; ++r1)
            s += c0[(i1 * 8 + o1) * 8 + r1] * c1[((r1 * 8 + i2) * 8 + o2) * 8 + r2];
        g_AT[t] = s;
    } else {
        // g_B2[k*64 + n], k=(r2,i3,i4), n=(o3,o4)
        int u = t - 32768;
        int k = u >> 6, n = u & 63;
        int r2 = k >> 6, i3 = (k >> 3) & 7, i4 = k & 7;
        int o3 = n >> 3, o4 = n & 7;
        float s = 0.0f;
#pragma unroll
        for (int r3 = 0; r3 < 8; ++r3)
            s += c2[((r2 * 8 + i3) * 8 + o3) * 8 + r3] * c3[(r3 * 8 + i4) * 8 + o4];
        g_B2[u] = s;
    }
}

// ---------------------------------------------------------------------------
// GEMM1: per CTA, 8 batch rows. C(512x64) = A(512x64,SMEM-stationary) x Bx(64x64).
// 512 threads, 8x8 register tile per thread, f32x2 packed accumulators.
// ---------------------------------------------------------------------------
__global__ __launch_bounds__(512, 1) void k_gemm1(const float* __restrict__ x) {
    extern __shared__ float smem[];
    float* sAT = smem;           // 32768 floats: [k=64][m=512]
    float* sB  = smem + 32768;   //  4096 floats: [k=64][n=64]
    const int tid = threadIdx.x;
    const int b0  = blockIdx.x * 8;

    // load stationary A^T once per CTA
    for (int i = tid; i < 8192; i += 512)
        ((float4*)sAT)[i] = ((const float4*)g_AT)[i];

    const int tm = tid >> 3, tn = tid & 7;
    const int m0 = tm * 8,   n0 = tn * 8;

    // prefetch first x row into registers
    const float4* xb4 = (const float4*)(x + (size_t)b0 * 4096);
    float4 rx0 = xb4[tid];
    float4 rx1 = xb4[tid + 512];

    for (int j = 0; j < 8; ++j) {
        ((float4*)sB)[tid]       = rx0;
        ((float4*)sB)[tid + 512] = rx1;
        __syncthreads();
        if (j < 7) {  // prefetch next row, latency hidden by compute
            const float4* xn = (const float4*)(x + (size_t)(b0 + j + 1) * 4096);
            rx0 = xn[tid];
            rx1 = xn[tid + 512];
        }

        unsigned long long acc[8][4];
#pragma unroll
        for (int i = 0; i < 8; ++i)
#pragma unroll
            for (int q = 0; q < 4; ++q) acc[i][q] = 0ull;

#pragma unroll 8
        for (int k = 0; k < 64; ++k) {
            const float4* ar = (const float4*)(sAT + k * 512 + m0);
            float4 a0 = ar[0], a1 = ar[1];
            const ulonglong2* br = (const ulonglong2*)(sB + k * 64 + n0);
            ulonglong2 bb0 = br[0], bb1 = br[1];
            float av[8] = {a0.x, a0.y, a0.z, a0.w, a1.x, a1.y, a1.z, a1.w};
#pragma unroll
            for (int i = 0; i < 8; ++i) {
                unsigned long long a2 = pack2(av[i]);
                ffma2(acc[i][0], a2, bb0.x);
                ffma2(acc[i][1], a2, bb0.y);
                ffma2(acc[i][2], a2, bb1.x);
                ffma2(acc[i][3], a2, bb1.y);
            }
        }

        float* zb = g_z1 + (size_t)(b0 + j) * 32768;
#pragma unroll
        for (int i = 0; i < 8; ++i) {
            ulonglong2* dst = (ulonglong2*)(zb + (m0 + i) * 64 + n0);
            ulonglong2 s0, s1;
            s0.x = acc[i][0]; s0.y = acc[i][1];
            s1.x = acc[i][2]; s1.y = acc[i][3];
            dst[0] = s0; dst[1] = s1;
        }
        __syncthreads();  // all reads of sB done before next row overwrite
    }
}

// ---------------------------------------------------------------------------
// GEMM2: per CTA, 8 batch rows folded into the M dim.
// C(512x64) = A(512x512, streamed K-chunks from z1) x G23(512x64, SMEM-stationary)
// A chunks transposed into SMEM, double-buffered with register prefetch.
// ---------------------------------------------------------------------------
__global__ __launch_bounds__(512, 1) void k_gemm2(const float* __restrict__ bias,
                                                  float* __restrict__ out) {
    extern __shared__ float smem[];
    float* sB2 = smem;           // 32768 floats: [k=512][n=64]
    float* sA  = smem + 32768;   // 2 buffers of [kk=16][m=512 (+4 pad)] = 2*8256
    const int tid = threadIdx.x;
    const int b0  = blockIdx.x * 8;
    const float* zb = g_z1 + (size_t)b0 * 32768;

    for (int i = tid; i < 8192; i += 512)
        ((float4*)sB2)[i] = ((const float4*)g_B2)[i];

    // per-thread fixed transpose coordinates: kk = tid&15, base row = tid>>4
    const int kkw = tid & 15;
    const int Rw  = tid >> 4;

    // prime chunk 0
#pragma unroll
    for (int j = 0; j < 16; ++j) {
        int R = Rw + 32 * j;
        sA[kkw * 516 + R] = zb[(size_t)R * 512 + kkw];
    }
    __syncthreads();

    const int tm = tid >> 3, tn = tid & 7;
    const int m0 = tm * 8,   n0 = tn * 8;

    unsigned long long acc[8][4];
#pragma unroll
    for (int i = 0; i < 8; ++i)
#pragma unroll
        for (int q = 0; q < 4; ++q) acc[i][q] = 0ull;

    float rv[16];
    for (int c = 0; c < 32; ++c) {
        const float* sAc = sA + (c & 1) * 8256;
        if (c < 31) {  // issue prefetch loads for next chunk (latency under compute)
            int kb = (c + 1) * 16 + kkw;
#pragma unroll
            for (int j = 0; j < 16; ++j) {
                int R = Rw + 32 * j;
                rv[j] = zb[(size_t)R * 512 + kb];
            }
        }
#pragma unroll 4
        for (int kk = 0; kk < 16; ++kk) {
            int k = c * 16 + kk;
            const float4* ar = (const float4*)(sAc + kk * 516 + m0);
            float4 a0 = ar[0], a1 = ar[1];
            const ulonglong2* br = (const ulonglong2*)(sB2 + k * 64 + n0);
            ulonglong2 bb0 = br[0], bb1 = br[1];
            float av[8] = {a0.x, a0.y, a0.z, a0.w, a1.x, a1.y, a1.z, a1.w};
#pragma unroll
            for (int i = 0; i < 8; ++i) {
                unsigned long long a2 = pack2(av[i]);
                ffma2(acc[i][0], a2, bb0.x);
                ffma2(acc[i][1], a2, bb0.y);
                ffma2(acc[i][2], a2, bb1.x);
                ffma2(acc[i][3], a2, bb1.y);
            }
        }
        if (c < 31) {  // store prefetched chunk into the other buffer
            float* sAn = sA + ((c + 1) & 1) * 8256;
#pragma unroll
            for (int j = 0; j < 16; ++j) {
                int R = Rw + 32 * j;
                sAn[kkw * 516 + R] = rv[j];
            }
        }
        __syncthreads();
    }

    // epilogue: unpack, add bias, store
#pragma unroll
    for (int i = 0; i < 8; ++i) {
        int R = m0 + i;
        int bprime = R >> 6, o12 = R & 63;
        float* dst = out + (size_t)(b0 + bprime) * 4096 + o12 * 64 + n0;
        const float4* bs = (const float4*)(bias + o12 * 64 + n0);
        float4 bv0 = bs[0], bv1 = bs[1];
        U2F u0, u1, u2, u3;
        u0.u = acc[i][0]; u1.u = acc[i][1]; u2.u = acc[i][2]; u3.u = acc[i][3];
        float4 r0, r1;
        r0.x = u0.f.x + bv0.x; r0.y = u0.f.y + bv0.y;
        r0.z = u1.f.x + bv0.z; r0.w = u1.f.y + bv0.w;
        r1.x = u2.f.x + bv1.x; r1.y = u2.f.y + bv1.y;
        r1.z = u3.f.x + bv1.z; r1.w = u3.f.y + bv1.w;
        ((float4*)dst)[0] = r0;
        ((float4*)dst)[1] = r1;
    }
}

// ---------------------------------------------------------------------------
extern "C" void kernel_launch(void* const* d_in, const int* in_sizes, int n_in,
                              void* d_out, int out_size) {
    (void)in_sizes; (void)n_in; (void)out_size;
    const float* x    = (const float*)d_in[0];
    const float* c0   = (const float*)d_in[1];
    const float* c1   = (const float*)d_in[2];
    const float* c2   = (const float*)d_in[3];
    const float* c3   = (const float*)d_in[4];
    const float* bias = (const float*)d_in[5];
    float* out = (float*)d_out;

    cudaFuncSetAttribute(k_gemm1, cudaFuncAttributeMaxDynamicSharedMemorySize, 147456);
    cudaFuncSetAttribute(k_gemm2, cudaFuncAttributeMaxDynamicSharedMemorySize, 197120);

    k_prep<<<256, 256>>>(c0, c1, c2, c3);
    k_gemm1<<<512, 512, 147456>>>(x);          // 512 CTAs x 8 batch rows
    k_gemm2<<<512, 512, 197120>>>(bias, out);  // 512 CTAs x 8 batch rows
}

// round 4
// speedup vs baseline: 1.0512x; 1.0512x over previous
#include <cuda_runtime.h>
#include <cstdint>
#include <cstddef>

// ============================================================================
// TT-Linear as two merged GEMMs, fp32 with packed f32x2 FFMA.
//
//   G01[(o1,o2,r2)][(i1,i2)] = sum_r1 core0[i1,o1,r1] * core1[r1,i2,o2,r2]
//   G23[(r2,i3,i4)][(o3,o4)] = sum_r3 core2[r2,i3,o3,r3] * core3[r3,i4,o4]
//
//   GEMM1: z1[b][(o12,r2)][(i34)] = G01 (512x64) @ x_b (64x64)
//   GEMM2: y[b][(o12)][(o34)]    = z1_b (64x512) @ G23 (512x64) + bias
//
// z1 flat layout b*32768 + (o12*8+r2)*64 + i34 == b*32768 + o12*512 + (r2*64+i34)
// serves both GEMMs without any transpose.
// ============================================================================

__device__ __align__(16) float g_AT[64 * 512];   // G01 transposed: [k=i12][m=(o1,o2,r2)]
__device__ __align__(16) float g_B2[512 * 64];   // G23:            [k=(r2,i3,i4)][n=(o3,o4)]
__device__ __align__(16) float g_z1[134217728];  // [b=4096][m=512][n=64]  (512 MiB scratch)

__device__ __forceinline__ unsigned long long pack2(float v) {
    unsigned long long r;
    asm("mov.b64 %0, {%1, %1};" : "=l"(r) : "f"(v));
    return r;
}
__device__ __forceinline__ void ffma2(unsigned long long& d,
                                      unsigned long long a,
                                      unsigned long long b) {
    // packed 2-lane fp32 fma: d.lo += a.lo*b.lo ; d.hi += a.hi*b.hi
    asm("fma.rn.f32x2 %0, %1, %2, %0;" : "+l"(d) : "l"(a), "l"(b));
}

union U2F { unsigned long long u; float2 f; };

// ---------------------------------------------------------------------------
// Merge the TT cores into G01^T and G23. 65536 entries, 8 MACs each.
// ---------------------------------------------------------------------------
__global__ void k_prep(const float* __restrict__ c0, const float* __restrict__ c1,
                       const float* __restrict__ c2, const float* __restrict__ c3) {
    int t = blockIdx.x * blockDim.x + threadIdx.x;  // 0..65535
    if (t < 32768) {
        // g_AT[k*512 + m], k=(i1,i2), m=(o1,o2,r2)
        int k = t >> 9, m = t & 511;
        int i1 = k >> 3, i2 = k & 7;
        int o1 = m >> 6, o2 = (m >> 3) & 7, r2 = m & 7;
        float s = 0.0f;
#pragma unroll
        for (int r1 = 0; r1 < 8; ++r1)
            s += c0[(i1 * 8 + o1) * 8 + r1] * c1[((r1 * 8 + i2) * 8 + o2) * 8 + r2];
        g_AT[t] = s;
    } else {
        // g_B2[k*64 + n], k=(r2,i3,i4), n=(o3,o4)
        int u = t - 32768;
        int k = u >> 6, n = u & 63;
        int r2 = k >> 6, i3 = (k >> 3) & 7, i4 = k & 7;
        int o3 = n >> 3, o4 = n & 7;
        float s = 0.0f;
#pragma unroll
        for (int r3 = 0; r3 < 8; ++r3)
            s += c2[((r2 * 8 + i3) * 8 + o3) * 8 + r3] * c3[(r3 * 8 + i4) * 8 + o4];
        g_B2[u] = s;
    }
}

// ---------------------------------------------------------------------------
// GEMM1: per CTA, 8 batch rows. C(512x64) = A(512x64,SMEM-stationary) x Bx(64x64).
// 512 threads, 8x8 register tile per thread, f32x2 packed accumulators.
// ---------------------------------------------------------------------------
__global__ __launch_bounds__(512, 1) void k_gemm1(const float* __restrict__ x) {
    extern __shared__ float smem[];
    float* sAT = smem;           // 32768 floats: [k=64][m=512]
    float* sB  = smem + 32768;   //  4096 floats: [k=64][n=64]
    const int tid = threadIdx.x;
    const int b0  = blockIdx.x * 8;

    // load stationary A^T once per CTA
    for (int i = tid; i < 8192; i += 512)
        ((float4*)sAT)[i] = ((const float4*)g_AT)[i];

    const int tm = tid >> 3, tn = tid & 7;
    const int m0 = tm * 8,   n0 = tn * 8;

    // prefetch first x row into registers
    const float4* xb4 = (const float4*)(x + (size_t)b0 * 4096);
    float4 rx0 = xb4[tid];
    float4 rx1 = xb4[tid + 512];

    for (int j = 0; j < 8; ++j) {
        ((float4*)sB)[tid]       = rx0;
        ((float4*)sB)[tid + 512] = rx1;
        __syncthreads();
        if (j < 7) {  // prefetch next row, latency hidden by compute
            const float4* xn = (const float4*)(x + (size_t)(b0 + j + 1) * 4096);
            rx0 = xn[tid];
            rx1 = xn[tid + 512];
        }

        unsigned long long acc[8][4];
#pragma unroll
        for (int i = 0; i < 8; ++i)
#pragma unroll
            for (int q = 0; q < 4; ++q) acc[i][q] = 0ull;

#pragma unroll 8
        for (int k = 0; k < 64; ++k) {
            const float4* ar = (const float4*)(sAT + k * 512 + m0);
            float4 a0 = ar[0], a1 = ar[1];
            const ulonglong2* br = (const ulonglong2*)(sB + k * 64 + n0);
            ulonglong2 bb0 = br[0], bb1 = br[1];
            float av[8] = {a0.x, a0.y, a0.z, a0.w, a1.x, a1.y, a1.z, a1.w};
#pragma unroll
            for (int i = 0; i < 8; ++i) {
                unsigned long long a2 = pack2(av[i]);
                ffma2(acc[i][0], a2, bb0.x);
                ffma2(acc[i][1], a2, bb0.y);
                ffma2(acc[i][2], a2, bb1.x);
                ffma2(acc[i][3], a2, bb1.y);
            }
        }

        float* zb = g_z1 + (size_t)(b0 + j) * 32768;
#pragma unroll
        for (int i = 0; i < 8; ++i) {
            ulonglong2* dst = (ulonglong2*)(zb + (m0 + i) * 64 + n0);
            ulonglong2 s0, s1;
            s0.x = acc[i][0]; s0.y = acc[i][1];
            s1.x = acc[i][2]; s1.y = acc[i][3];
            dst[0] = s0; dst[1] = s1;
        }
        __syncthreads();  // all reads of sB done before next row overwrite
    }
}

// ---------------------------------------------------------------------------
// GEMM2: per CTA, 8 batch rows folded into the M dim.
// C(512x64) = A(512x512, streamed K-chunks from z1) x G23(512x64, SMEM-stationary)
// A chunks transposed into SMEM, double-buffered with register prefetch.
// ---------------------------------------------------------------------------
__global__ __launch_bounds__(512, 1) void k_gemm2(const float* __restrict__ bias,
                                                  float* __restrict__ out) {
    extern __shared__ float smem[];
    float* sB2 = smem;           // 32768 floats: [k=512][n=64]
    float* sA  = smem + 32768;   // 2 buffers of [kk=16][m=512 (+4 pad)] = 2*8256
    const int tid = threadIdx.x;
    const int b0  = blockIdx.x * 8;
    const float* zb = g_z1 + (size_t)b0 * 32768;

    for (int i = tid; i < 8192; i += 512)
        ((float4*)sB2)[i] = ((const float4*)g_B2)[i];

    // per-thread fixed transpose coordinates: kk = tid&15, base row = tid>>4
    const int kkw = tid & 15;
    const int Rw  = tid >> 4;

    // prime chunk 0
#pragma unroll
    for (int j = 0; j < 16; ++j) {
        int R = Rw + 32 * j;
        sA[kkw * 516 + R] = zb[(size_t)R * 512 + kkw];
    }
    __syncthreads();

    const int tm = tid >> 3, tn = tid & 7;
    const int m0 = tm * 8,   n0 = tn * 8;

    unsigned long long acc[8][4];
#pragma unroll
    for (int i = 0; i < 8; ++i)
#pragma unroll
        for (int q = 0; q < 4; ++q) acc[i][q] = 0ull;

    float rv[16];
    for (int c = 0; c < 32; ++c) {
        const float* sAc = sA + (c & 1) * 8256;
        if (c < 31) {  // issue prefetch loads for next chunk (latency under compute)
            int kb = (c + 1) * 16 + kkw;
#pragma unroll
            for (int j = 0; j < 16; ++j) {
                int R = Rw + 32 * j;
                rv[j] = zb[(size_t)R * 512 + kb];
            }
        }
#pragma unroll 4
        for (int kk = 0; kk < 16; ++kk) {
            int k = c * 16 + kk;
            const float4* ar = (const float4*)(sAc + kk * 516 + m0);
            float4 a0 = ar[0], a1 = ar[1];
            const ulonglong2* br = (const ulonglong2*)(sB2 + k * 64 + n0);
            ulonglong2 bb0 = br[0], bb1 = br[1];
            float av[8] = {a0.x, a0.y, a0.z, a0.w, a1.x, a1.y, a1.z, a1.w};
#pragma unroll
            for (int i = 0; i < 8; ++i) {
                unsigned long long a2 = pack2(av[i]);
                ffma2(acc[i][0], a2, bb0.x);
                ffma2(acc[i][1], a2, bb0.y);
                ffma2(acc[i][2], a2, bb1.x);
                ffma2(acc[i][3], a2, bb1.y);
            }
        }
        if (c < 31) {  // store prefetched chunk into the other buffer
            float* sAn = sA + ((c + 1) & 1) * 8256;
#pragma unroll
            for (int j = 0; j < 16; ++j) {
                int R = Rw + 32 * j;
                sAn[kkw * 516 + R] = rv[j];
            }
        }
        __syncthreads();
    }

    // epilogue: unpack, add bias, store
#pragma unroll
    for (int i = 0; i < 8; ++i) {
        int R = m0 + i;
        int bprime = R >> 6, o12 = R & 63;
        float* dst = out + (size_t)(b0 + bprime) * 4096 + o12 * 64 + n0;
        const float4* bs = (const float4*)(bias + o12 * 64 + n0);
        float4 bv0 = bs[0], bv1 = bs[1];
        U2F u0, u1, u2, u3;
        u0.u = acc[i][0]; u1.u = acc[i][1]; u2.u = acc[i][2]; u3.u = acc[i][3];
        float4 r0, r1;
        r0.x = u0.f.x + bv0.x; r0.y = u0.f.y + bv0.y;
        r0.z = u1.f.x + bv0.z; r0.w = u1.f.y + bv0.w;
        r1.x = u2.f.x + bv1.x; r1.y = u2.f.y + bv1.y;
        r1.z = u3.f.x + bv1.z; r1.w = u3.f.y + bv1.w;
        ((float4*)dst)[0] = r0;
        ((float4*)dst)[1] = r1;
    }
}

// ---------------------------------------------------------------------------
extern "C" void kernel_launch(void* const* d_in, const int* in_sizes, int n_in,
                              void* d_out, int out_size) {
    (void)in_sizes; (void)n_in; (void)out_size;
    const float* x    = (const float*)d_in[0];
    const float* c0   = (const float*)d_in[1];
    const float* c1   = (const float*)d_in[2];
    const float* c2   = (const float*)d_in[3];
    const float* c3   = (const float*)d_in[4];
    const float* bias = (const float*)d_in[5];
    float* out = (float*)d_out;

    cudaFuncSetAttribute(k_gemm1, cudaFuncAttributeMaxDynamicSharedMemorySize, 147456);
    cudaFuncSetAttribute(k_gemm2, cudaFuncAttributeMaxDynamicSharedMemorySize, 197120);

    k_prep<<<256, 256>>>(c0, c1, c2, c3);
    k_gemm1<<<512, 512, 147456>>>(x);          // 512 CTAs x 8 batch rows
    k_gemm2<<<512, 512, 197120>>>(bias, out);  // 512 CTAs x 8 batch rows
}

// round 5
// speedup vs baseline: 1.1978x; 1.1394x over previous
#include <cuda_runtime.h>
#include <cstdint>
#include <cstddef>

// ============================================================================
// TT-Linear as two merged GEMMs, fp32 with packed f32x2 FFMA.
//
//   G01[(o1,o2,r2)][(i1,i2)] = sum_r1 core0[i1,o1,r1] * core1[r1,i2,o2,r2]
//   G23[(r2,i3,i4)][(o3,o4)] = sum_r3 core2[r2,i3,o3,r3] * core3[r3,i4,o4]
//
//   GEMM1: z1[b][(o12,r2)][(i34)] = G01 (512x64) @ x_b (64x64)
//   GEMM2: y[b][(o12)][(o34)]    = z1_b (64x512) @ G23 (512x64) + bias
//
// z1 flat layout b*32768 + (o12*8+r2)*64 + i34 == b*32768 + o12*512 + (r2*64+i34)
// serves both GEMMs without any transpose in global memory.
//
// This round: 16x8 register tiles (FMA-limited, LDS at 75% duty), 256 thr/CTA,
// persistent CTAs (stationary operands loaded once per CTA), conflict-free
// GEMM2 chunk transpose.
// ============================================================================

__device__ __align__(16) float g_AT[64 * 512];   // G01^T: [k=i12][m=(o1,o2,r2)]
__device__ __align__(16) float g_B2[512 * 64];   // G23:   [k=(r2,i3,i4)][n=(o3,o4)]
__device__ __align__(16) float g_z1[134217728];  // [b=4096][m=512][n=64]

__device__ __forceinline__ unsigned long long pack2(float v) {
    unsigned long long r;
    asm("mov.b64 %0, {%1, %1};" : "=l"(r) : "f"(v));
    return r;
}
__device__ __forceinline__ void ffma2(unsigned long long& d,
                                      unsigned long long a,
                                      unsigned long long b) {
    asm("fma.rn.f32x2 %0, %1, %2, %0;" : "+l"(d) : "l"(a), "l"(b));
}

union U2F { unsigned long long u; float2 f; };

// ---------------------------------------------------------------------------
// Merge TT cores into G01^T and G23. 65536 entries, 8 MACs each. ~4.5us.
// ---------------------------------------------------------------------------
__global__ void k_prep(const float* __restrict__ c0, const float* __restrict__ c1,
                       const float* __restrict__ c2, const float* __restrict__ c3) {
    int t = blockIdx.x * blockDim.x + threadIdx.x;  // 0..65535
    if (t < 32768) {
        int k = t >> 9, m = t & 511;
        int i1 = k >> 3, i2 = k & 7;
        int o1 = m >> 6, o2 = (m >> 3) & 7, r2 = m & 7;
        float s = 0.0f;
#pragma unroll
        for (int r1 = 0; r1 < 8; ++r1)
            s += c0[(i1 * 8 + o1) * 8 + r1] * c1[((r1 * 8 + i2) * 8 + o2) * 8 + r2];
        g_AT[t] = s;
    } else {
        int u = t - 32768;
        int k = u >> 6, n = u & 63;
        int r2 = k >> 6, i3 = (k >> 3) & 7, i4 = k & 7;
        int o3 = n >> 3, o4 = n & 7;
        float s = 0.0f;
#pragma unroll
        for (int r3 = 0; r3 < 8; ++r3)
            s += c2[((r2 * 8 + i3) * 8 + o3) * 8 + r3] * c3[(r3 * 8 + i4) * 8 + o4];
        g_B2[u] = s;
    }
}

// ---------------------------------------------------------------------------
// GEMM1: persistent CTAs grid-stride over batch rows.
// Per row: C(512x64) = A^T-stationary(64k x 512m, SMEM) x x_row(64k x 64n).
// 256 threads, 16(m) x 8(n) register tile, f32x2 packed accumulators.
// ---------------------------------------------------------------------------
__global__ __launch_bounds__(256, 1) void k_gemm1(const float* __restrict__ x) {
    extern __shared__ float smem[];
    float* sAT = smem;           // 32768 floats: [k=64][m=512]
    float* sB  = smem + 32768;   //  4096 floats: [k=64][n=64]
    const int tid = threadIdx.x;

    // stationary A^T, loaded once per CTA
    for (int i = tid; i < 8192; i += 256)
        ((float4*)sAT)[i] = ((const float4*)g_AT)[i];

    const int tm = tid >> 3, tn = tid & 7;   // tm 0..31, tn 0..7
    const int m0 = tm * 16,  n0 = tn * 8;

    int b = blockIdx.x;
    float4 rx[4];
    {
        const float4* xb4 = (const float4*)(x + (size_t)b * 4096);
#pragma unroll
        for (int p = 0; p < 4; ++p) rx[p] = xb4[tid + 256 * p];
    }

    for (; b < 4096; b += gridDim.x) {
#pragma unroll
        for (int p = 0; p < 4; ++p) ((float4*)sB)[tid + 256 * p] = rx[p];
        __syncthreads();

        int bn = b + gridDim.x;
        if (bn < 4096) {  // prefetch next row under compute
            const float4* xn = (const float4*)(x + (size_t)bn * 4096);
#pragma unroll
            for (int p = 0; p < 4; ++p) rx[p] = xn[tid + 256 * p];
        }

        unsigned long long acc[16][4];
#pragma unroll
        for (int i = 0; i < 16; ++i)
#pragma unroll
            for (int q = 0; q < 4; ++q) acc[i][q] = 0ull;

#pragma unroll 4
        for (int k = 0; k < 64; ++k) {
            const float4* ar = (const float4*)(sAT + k * 512 + m0);
            float4 a0 = ar[0], a1 = ar[1], a2 = ar[2], a3 = ar[3];
            const ulonglong2* br = (const ulonglong2*)(sB + k * 64 + n0);
            ulonglong2 bb0 = br[0], bb1 = br[1];
            float av[16] = {a0.x, a0.y, a0.z, a0.w, a1.x, a1.y, a1.z, a1.w,
                            a2.x, a2.y, a2.z, a2.w, a3.x, a3.y, a3.z, a3.w};
#pragma unroll
            for (int i = 0; i < 16; ++i) {
                unsigned long long ap = pack2(av[i]);
                ffma2(acc[i][0], ap, bb0.x);
                ffma2(acc[i][1], ap, bb0.y);
                ffma2(acc[i][2], ap, bb1.x);
                ffma2(acc[i][3], ap, bb1.y);
            }
        }

        float* zb = g_z1 + (size_t)b * 32768;
#pragma unroll
        for (int i = 0; i < 16; ++i) {
            ulonglong2 s0, s1;
            s0.x = acc[i][0]; s0.y = acc[i][1];
            s1.x = acc[i][2]; s1.y = acc[i][3];
            ulonglong2* dst = (ulonglong2*)(zb + (m0 + i) * 64 + n0);
            dst[0] = s0; dst[1] = s1;
        }
        __syncthreads();  // all sB reads done before next row overwrite
    }
}

// ---------------------------------------------------------------------------
// GEMM2: persistent CTAs grid-stride over 8-row batch groups.
// Per group: C(512x64) = A(512m x 512k, streamed from z1, transposed in SMEM)
//                       x G23-stationary(512k x 64n, SMEM, loaded once/CTA).
// Chunk = 8 k-slices, double-buffered, conflict-free STS (pad 516).
// ---------------------------------------------------------------------------
__global__ __launch_bounds__(256, 1) void k_gemm2(const float* __restrict__ bias,
                                                  float* __restrict__ out) {
    extern __shared__ float smem[];
    float* sB2 = smem;           // 32768 floats: [k=512][n=64]
    float* sA  = smem + 32768;   // 2 buffers of [kk=8][m=512 (+4 pad)] = 2*4128
    const int tid = threadIdx.x;

    for (int i = tid; i < 8192; i += 256)
        ((float4*)sB2)[i] = ((const float4*)g_B2)[i];

    const int kkw = tid & 7;       // k within chunk
    const int Rw  = tid >> 3;      // 0..31, row base
    const int tm = tid >> 3, tn = tid & 7;
    const int m0 = tm * 16,  n0 = tn * 8;

    for (int g = blockIdx.x; g < 512; g += gridDim.x) {
        const int b0 = g * 8;
        const float* zb = g_z1 + (size_t)b0 * 32768;

        // prime chunk 0 into buffer 0 (also orders sB2 before first compute)
#pragma unroll
        for (int j = 0; j < 16; ++j) {
            int R = Rw + 32 * j;
            sA[kkw * 516 + R] = zb[(size_t)R * 512 + kkw];
        }
        __syncthreads();

        unsigned long long acc[16][4];
#pragma unroll
        for (int i = 0; i < 16; ++i)
#pragma unroll
            for (int q = 0; q < 4; ++q) acc[i][q] = 0ull;

        float rv[16];
        for (int c = 0; c < 64; ++c) {
            const float* sAc = sA + (c & 1) * 4128;
            if (c < 63) {  // prefetch next chunk's LDG under compute
                int kb = (c + 1) * 8 + kkw;
#pragma unroll
                for (int j = 0; j < 16; ++j)
                    rv[j] = zb[(size_t)(Rw + 32 * j) * 512 + kb];
            }
#pragma unroll
            for (int kk = 0; kk < 8; ++kk) {
                int k = c * 8 + kk;
                const float4* ar = (const float4*)(sAc + kk * 516 + m0);
                float4 a0 = ar[0], a1 = ar[1], a2 = ar[2], a3 = ar[3];
                const ulonglong2* br = (const ulonglong2*)(sB2 + k * 64 + n0);
                ulonglong2 bb0 = br[0], bb1 = br[1];
                float av[16] = {a0.x, a0.y, a0.z, a0.w, a1.x, a1.y, a1.z, a1.w,
                                a2.x, a2.y, a2.z, a2.w, a3.x, a3.y, a3.z, a3.w};
#pragma unroll
                for (int i = 0; i < 16; ++i) {
                    unsigned long long ap = pack2(av[i]);
                    ffma2(acc[i][0], ap, bb0.x);
                    ffma2(acc[i][1], ap, bb0.y);
                    ffma2(acc[i][2], ap, bb1.x);
                    ffma2(acc[i][3], ap, bb1.y);
                }
            }
            if (c < 63) {  // store prefetched chunk into the other buffer
                float* sAn = sA + ((c + 1) & 1) * 4128;
#pragma unroll
                for (int j = 0; j < 16; ++j)
                    sAn[kkw * 516 + (Rw + 32 * j)] = rv[j];
            }
            __syncthreads();
        }

        // epilogue: unpack, add bias, store
#pragma unroll
        for (int i = 0; i < 16; ++i) {
            int R = m0 + i;
            int bprime = R >> 6, o12 = R & 63;
            float* dst = out + (size_t)(b0 + bprime) * 4096 + o12 * 64 + n0;
            const float4* bs = (const float4*)(bias + o12 * 64 + n0);
            float4 bv0 = bs[0], bv1 = bs[1];
            U2F u0, u1, u2, u3;
            u0.u = acc[i][0]; u1.u = acc[i][1]; u2.u = acc[i][2]; u3.u = acc[i][3];
            float4 r0, r1;
            r0.x = u0.f.x + bv0.x; r0.y = u0.f.y + bv0.y;
            r0.z = u1.f.x + bv0.z; r0.w = u1.f.y + bv0.w;
            r1.x = u2.f.x + bv1.x; r1.y = u2.f.y + bv1.y;
            r1.z = u3.f.x + bv1.z; r1.w = u3.f.y + bv1.w;
            ((float4*)dst)[0] = r0;
            ((float4*)dst)[1] = r1;
        }
        // (no extra sync needed: last k-iter's __syncthreads already ordered
        //  all sA reads; next group's prime writes come after it)
    }
}

// ---------------------------------------------------------------------------
extern "C" void kernel_launch(void* const* d_in, const int* in_sizes, int n_in,
                              void* d_out, int out_size) {
    (void)in_sizes; (void)n_in; (void)out_size;
    const float* x    = (const float*)d_in[0];
    const float* c0   = (const float*)d_in[1];
    const float* c1   = (const float*)d_in[2];
    const float* c2   = (const float*)d_in[3];
    const float* c3   = (const float*)d_in[4];
    const float* bias = (const float*)d_in[5];
    float* out = (float*)d_out;

    cudaFuncSetAttribute(k_gemm1, cudaFuncAttributeMaxDynamicSharedMemorySize, 147456);
    cudaFuncSetAttribute(k_gemm2, cudaFuncAttributeMaxDynamicSharedMemorySize, 164096);

    k_prep<<<256, 256>>>(c0, c1, c2, c3);
    k_gemm1<<<152, 256, 147456>>>(x);          // persistent: grid-stride batch rows
    k_gemm2<<<152, 256, 164096>>>(bias, out);  // persistent: grid-stride 8-row groups
}

// round 7
// speedup vs baseline: 2.1097x; 1.7614x over previous
#include <cuda_runtime.h>
#include <cuda_bf16.h>
#include <cstdint>
#include <cstddef>

// ============================================================================
// TT-Linear as two merged GEMMs on HMMA (mma.sync bf16, baseline PTX — the
// harness compiles PTX for compute_103 without 'a', so tcgen05 is unavailable).
//
//   G01[m=(o1,o2,r2)][k=(i1,i2)]  (512x64)
//   G23t[n=(o3,o4)][k2=(r2,i3,i4)] (64x512)
//   stage1: z[b][m=512][i34] = G01 @ x_b^T          (K=64)
//   stage2: y[(b,o12)][o34]  = z_rows @ G23 + bias  (K=512)
//
// All bf16 operands stored as interleaved {hi,lo} 32-bit words; fragments are
// split with PRMT. 3-term split per GEMM: Ah*Bh + Ah*Bl + Al*Bh.
// z flat word layout [b][m][i34]: row (b,o12) is 512 contiguous words = exactly
// stage-2's K vector (r2*64+i34). out rows are (b*64+o12)*64 + o34 contiguous.
// ============================================================================

__device__ __align__(16) uint32_t g_A[512 * 64];          // G01 {h,l} words [m][k]
__device__ __align__(16) uint32_t g_B[64 * 512];          // G23t {h,l} words [n][k2]
__device__ __align__(16) uint32_t g_XT[4096u * 4096u];    // x^T {h,l} words [b][i34][i12]
__device__ __align__(16) uint32_t g_Z[134217728u];        // z {h,l} words [b][m][i34]

// ---------------------------------------------------------------- helpers
__device__ __forceinline__ uint32_t prmt(uint32_t a, uint32_t b, uint32_t s) {
    uint32_t d;
    asm("prmt.b32 %0, %1, %2, %3;" : "=r"(d) : "r"(a), "r"(b), "r"(s));
    return d;
}
// pack float -> {bf16 hi (low16), bf16 lo-residual (high16)}
__device__ __forceinline__ uint32_t pack_hl(float f) {
    __nv_bfloat16 h = __float2bfloat16(f);
    float hf = __bfloat162float(h);
    __nv_bfloat16 l = __float2bfloat16(f - hf);
    return (uint32_t)__bfloat16_as_ushort(h) |
           ((uint32_t)__bfloat16_as_ushort(l) << 16);
}
// from two adjacent-k words {h,l}, build hi-plane / lo-plane bf16x2 regs
#define SPLIT_HL(w, H, L) do { H = prmt((w).x, (w).y, 0x5410); \
                               L = prmt((w).x, (w).y, 0x7632); } while (0)

__device__ __forceinline__ void mma16816(float* c, const uint32_t* a,
                                         const uint32_t* b) {
    asm volatile(
        "mma.sync.aligned.m16n8k16.row.col.f32.bf16.bf16.f32 "
        "{%0,%1,%2,%3}, {%4,%5,%6,%7}, {%8,%9}, {%0,%1,%2,%3};"
        : "+f"(c[0]), "+f"(c[1]), "+f"(c[2]), "+f"(c[3])
        : "r"(a[0]), "r"(a[1]), "r"(a[2]), "r"(a[3]), "r"(b[0]), "r"(b[1]));
}
__device__ __forceinline__ void cpa16(uint32_t dst_smem, const void* src) {
    asm volatile("cp.async.cg.shared.global [%0], [%1], 16;"
                 :: "r"(dst_smem), "l"(src) : "memory");
}
__device__ __forceinline__ void cpa_commit() {
    asm volatile("cp.async.commit_group;" ::: "memory");
}
__device__ __forceinline__ void cpa_wait0() {
    asm volatile("cp.async.wait_group 0;" ::: "memory");
}
__device__ __forceinline__ void cpa_wait1() {
    asm volatile("cp.async.wait_group 1;" ::: "memory");
}

// ---------------------------------------------------------------------------
// prep: merge core pairs and split to interleaved bf16 {h,l} words.
// ---------------------------------------------------------------------------
__global__ void k_prep(const float* __restrict__ c0, const float* __restrict__ c1,
                       const float* __restrict__ c2, const float* __restrict__ c3) {
    int t = blockIdx.x * blockDim.x + threadIdx.x;  // 0..65535
    if (t < 32768) {
        int m = t >> 6, k = t & 63;
        int o1 = m >> 6, o2 = (m >> 3) & 7, r2 = m & 7;
        int i1 = k >> 3, i2 = k & 7;
        float s = 0.0f;
#pragma unroll
        for (int r1 = 0; r1 < 8; ++r1)
            s += c0[(i1 * 8 + o1) * 8 + r1] * c1[((r1 * 8 + i2) * 8 + o2) * 8 + r2];
        g_A[t] = pack_hl(s);
    } else {
        int u = t - 32768;
        int n = u >> 9, k2 = u & 511;
        int o3 = n >> 3, o4 = n & 7;
        int r2 = k2 >> 6, i3 = (k2 >> 3) & 7, i4 = k2 & 7;
        float s = 0.0f;
#pragma unroll
        for (int r3 = 0; r3 < 8; ++r3)
            s += c2[((r2 * 8 + i3) * 8 + o3) * 8 + r3] * c3[(r3 * 8 + i4) * 8 + o4];
        g_B[u] = pack_hl(s);
    }
}

// ---------------------------------------------------------------------------
// splitXT: x[b][i12*64+i34] fp32 -> g_XT[b][i34][i12] {h,l} words (transposed).
// One CTA per batch row.
// ---------------------------------------------------------------------------
__global__ __launch_bounds__(256) void k_splitXT(const float* __restrict__ x) {
    __shared__ float sx[64 * 65];  // [i12][i34], pad 65 for conflict-free reads
    const int tid = threadIdx.x;
    const int b = blockIdx.x;
    const float4* src = (const float4*)(x + (size_t)b * 4096);
#pragma unroll
    for (int p = 0; p < 4; ++p) {
        float4 v = src[tid + 256 * p];
        int j = tid + 256 * p;               // float4 index
        int i12 = j >> 4, c = (j & 15) * 4;  // i34 base
        float* d = &sx[i12 * 65 + c];
        d[0] = v.x; d[1] = v.y; d[2] = v.z; d[3] = v.w;
    }
    __syncthreads();
    uint32_t* dst = g_XT + (size_t)b * 4096;
#pragma unroll
    for (int it = 0; it < 16; ++it) {
        int idx = it * 256 + tid;        // = i34*64 + i12
        int i34 = idx >> 6, i12 = idx & 63;
        dst[idx] = pack_hl(sx[i12 * 65 + i34]);
    }
}

// ---------------------------------------------------------------------------
// k1 (stage 1): z = G01 @ X^T.  Persistent: CTA fixes m-chunk (128 of 512),
// strides n-chunks (128 cols = 2 batch rows).  256 thr, warp tile 64m x 32n.
// SMEM: sA [128][72] words (G01 chunk), sB double buffer [128][72] x2.
// ---------------------------------------------------------------------------
__global__ __launch_bounds__(256, 1) void k1() {
    extern __shared__ uint32_t sm1[];
    uint32_t* sA = sm1;                      // 9216 words
    const int tid = threadIdx.x;
    const int lane = tid & 31, w = tid >> 5;
    const int g = lane >> 2, t4 = lane & 3;
    const int wm = w & 1, wn = w >> 1;       // 2 x 4 warp grid
    const int mc = blockIdx.x & 3;
    const int nc0 = blockIdx.x >> 2;         // 0..147

    // stationary A chunk: g_A rows mc*128..+127 (pitch 64 -> 72)
    {
        const uint4* src = (const uint4*)(g_A + mc * 8192);
        for (int j = tid; j < 2048; j += 256) {
            uint4 v = src[j];
            int row = j >> 4, c4 = (j & 15) << 2;
            *(uint4*)&sA[row * 72 + c4] = v;
        }
    }

    // prologue: async-load first B chunk into buffer 0
    int it = 0;
    {
        const char* src = (const char*)(g_XT + (size_t)nc0 * 8192);
        for (int j = tid; j < 512; j += 256) {     // 512 x 16B = 8KB? no: 8192 words=32KB -> 2048 uint4
        }
    }
    // (real prologue below — helper lambda-free, explicit)
    {
        uint32_t* sB = sm1 + 9216;
        const uint4* src = (const uint4*)(g_XT + (size_t)nc0 * 8192);
        for (int j = tid; j < 2048; j += 256) {
            int row = j >> 4, c4 = (j & 15) << 2;
            cpa16((uint32_t)__cvta_generic_to_shared(&sB[row * 72 + c4]), &src[j]);
        }
        cpa_commit();
    }

    for (int nc = nc0; nc < 2048; nc += 148, ++it) {
        uint32_t* sB = sm1 + 9216 + (it & 1) * 9216;
        int ncn = nc + 148;
        bool has_next = (ncn < 2048);
        if (has_next) {  // issue next chunk into the other buffer
            uint32_t* sBn = sm1 + 9216 + ((it + 1) & 1) * 9216;
            const uint4* src = (const uint4*)(g_XT + (size_t)ncn * 8192);
            for (int j = tid; j < 2048; j += 256) {
                int row = j >> 4, c4 = (j & 15) << 2;
                cpa16((uint32_t)__cvta_generic_to_shared(&sBn[row * 72 + c4]), &src[j]);
            }
            cpa_commit();
            cpa_wait1();   // current chunk done; next may be in flight
        } else {
            cpa_wait0();
        }
        __syncthreads();

        float acc[4][4][4];
#pragma unroll
        for (int a = 0; a < 4; ++a)
#pragma unroll
            for (int b = 0; b < 4; ++b)
#pragma unroll
                for (int q = 0; q < 4; ++q) acc[a][b][q] = 0.0f;

#pragma unroll
        for (int ks = 0; ks < 4; ++ks) {
            const int kA = ks * 16 + t4 * 2;
            uint32_t ah[4][4], al[4][4];
#pragma unroll
            for (int mt = 0; mt < 4; ++mt) {
                int row = wm * 64 + mt * 16 + g;
                uint2 w0 = *(const uint2*)&sA[row * 72 + kA];
                uint2 w1 = *(const uint2*)&sA[(row + 8) * 72 + kA];
                uint2 w2 = *(const uint2*)&sA[row * 72 + kA + 8];
                uint2 w3 = *(const uint2*)&sA[(row + 8) * 72 + kA + 8];
                SPLIT_HL(w0, ah[mt][0], al[mt][0]);
                SPLIT_HL(w1, ah[mt][1], al[mt][1]);
                SPLIT_HL(w2, ah[mt][2], al[mt][2]);
                SPLIT_HL(w3, ah[mt][3], al[mt][3]);
            }
#pragma unroll
            for (int nt = 0; nt < 4; ++nt) {
                int ncol = wn * 32 + nt * 8 + g;
                uint2 u0 = *(const uint2*)&sB[ncol * 72 + kA];
                uint2 u1 = *(const uint2*)&sB[ncol * 72 + kA + 8];
                uint32_t bh[2], bl_[2];
                SPLIT_HL(u0, bh[0], bl_[0]);
                SPLIT_HL(u1, bh[1], bl_[1]);
#pragma unroll
                for (int mt = 0; mt < 4; ++mt) {
                    mma16816(acc[mt][nt], ah[mt], bh);
                    mma16816(acc[mt][nt], ah[mt], bl_);
                    mma16816(acc[mt][nt], al[mt], bh);
                }
            }
        }

        // store z tile: interleaved {h,l} words, STG.64 (32B/quad coalesced)
        const int b0 = nc * 2;
#pragma unroll
        for (int mt = 0; mt < 4; ++mt) {
            int row = mc * 128 + wm * 64 + mt * 16 + g;
#pragma unroll
            for (int nt = 0; nt < 4; ++nt) {
                int ncol = wn * 32 + nt * 8 + t4 * 2;
                int bl2 = ncol >> 6, i34 = ncol & 63;
                size_t base = ((size_t)(b0 + bl2) * 512 + row) * 64 + i34;
                uint2 v0, v1;
                v0.x = pack_hl(acc[mt][nt][0]);
                v0.y = pack_hl(acc[mt][nt][1]);
                v1.x = pack_hl(acc[mt][nt][2]);
                v1.y = pack_hl(acc[mt][nt][3]);
                *(uint2*)&g_Z[base] = v0;
                *(uint2*)&g_Z[base + 8 * 64] = v1;
            }
        }
        __syncthreads();  // all sB reads done before it+1 overwrites this buffer
    }
}

// ---------------------------------------------------------------------------
// k2 (stage 2): y = Z @ G23 + bias.  Grid 1024, CTA = 256 rows of M=262144.
// G23 resident in SMEM ([64][520] words); Z streamed straight into A-frags
// via LDG.64 (lanes 0-3 cover 32B contiguous), 1-deep k-prefetch.
// ---------------------------------------------------------------------------
__global__ __launch_bounds__(256, 1) void k2(const float* __restrict__ bias,
                                             float* __restrict__ out) {
    extern __shared__ uint32_t sm2[];   // sB [64][520] = 33280 words (133120 B)
    uint32_t* sB = sm2;
    const int tid = threadIdx.x;
    const int lane = tid & 31, w = tid >> 5;
    const int g = lane >> 2, t4 = lane & 3;

    {
        const uint4* src = (const uint4*)g_B;
        for (int j = tid; j < 8192; j += 256) {
            uint4 v = src[j];
            int row = j >> 7, c4 = (j & 127) << 2;
            *(uint4*)&sB[row * 520 + c4] = v;
        }
    }

    // A row pointers: global row gidx = bx*256 + w*32 + mt*16 + g (+8)
    const uint32_t* p0[2];
    const uint32_t* p8[2];
#pragma unroll
    for (int mt = 0; mt < 2; ++mt) {
        size_t gr = (size_t)blockIdx.x * 256 + w * 32 + mt * 16 + g;
        p0[mt] = g_Z + gr * 512;
        p8[mt] = g_Z + (gr + 8) * 512;
    }

    float acc[2][8][4];
#pragma unroll
    for (int a = 0; a < 2; ++a)
#pragma unroll
        for (int b = 0; b < 8; ++b)
#pragma unroll
            for (int q = 0; q < 4; ++q) acc[a][b][q] = 0.0f;

    uint2 aw[2][2][4];  // [stage][mt][quad]
    {
        const int kA = t4 * 2;
#pragma unroll
        for (int mt = 0; mt < 2; ++mt) {
            aw[0][mt][0] = *(const uint2*)(p0[mt] + kA);
            aw[0][mt][1] = *(const uint2*)(p8[mt] + kA);
            aw[0][mt][2] = *(const uint2*)(p0[mt] + kA + 8);
            aw[0][mt][3] = *(const uint2*)(p8[mt] + kA + 8);
        }
    }
    __syncthreads();  // sB ready

    for (int ks = 0; ks < 32; ++ks) {
        const int cur = ks & 1;
        if (ks < 31) {  // prefetch next k-step's A words
            const int kA = (ks + 1) * 16 + t4 * 2;
#pragma unroll
            for (int mt = 0; mt < 2; ++mt) {
                aw[cur ^ 1][mt][0] = *(const uint2*)(p0[mt] + kA);
                aw[cur ^ 1][mt][1] = *(const uint2*)(p8[mt] + kA);
                aw[cur ^ 1][mt][2] = *(const uint2*)(p0[mt] + kA + 8);
                aw[cur ^ 1][mt][3] = *(const uint2*)(p8[mt] + kA + 8);
            }
        }
        uint32_t ah[2][4], al[2][4];
#pragma unroll
        for (int mt = 0; mt < 2; ++mt) {
            SPLIT_HL(aw[cur][mt][0], ah[mt][0], al[mt][0]);
            SPLIT_HL(aw[cur][mt][1], ah[mt][1], al[mt][1]);
            SPLIT_HL(aw[cur][mt][2], ah[mt][2], al[mt][2]);
            SPLIT_HL(aw[cur][mt][3], ah[mt][3], al[mt][3]);
        }
        const int kB = ks * 16 + t4 * 2;
#pragma unroll
        for (int nt = 0; nt < 8; ++nt) {
            int ncol = nt * 8 + g;
            uint2 u0 = *(const uint2*)&sB[ncol * 520 + kB];
            uint2 u1 = *(const uint2*)&sB[ncol * 520 + kB + 8];
            uint32_t bh[2], bl_[2];
            SPLIT_HL(u0, bh[0], bl_[0]);
            SPLIT_HL(u1, bh[1], bl_[1]);
#pragma unroll
            for (int mt = 0; mt < 2; ++mt) {
                mma16816(acc[mt][nt], ah[mt], bh);
                mma16816(acc[mt][nt], ah[mt], bl_);
                mma16816(acc[mt][nt], al[mt], bh);
            }
        }
    }

    // epilogue: +bias, store (out rows = (b*64+o12)*64 + o34, contiguous)
#pragma unroll
    for (int mt = 0; mt < 2; ++mt) {
        size_t grow0 = (size_t)blockIdx.x * 256 + w * 32 + mt * 16 + g;
#pragma unroll
        for (int half = 0; half < 2; ++half) {
            size_t grow = grow0 + half * 8;
            int o12 = (int)(grow & 63);
            float* orow = out + grow * 64;
            const int ci = half * 2;
#pragma unroll
            for (int nt = 0; nt < 8; ++nt) {
                int col = nt * 8 + t4 * 2;
                float2 bv = __ldg((const float2*)&bias[o12 * 64 + col]);
                float2 v;
                v.x = acc[mt][nt][ci] + bv.x;
                v.y = acc[mt][nt][ci + 1] + bv.y;
                *(float2*)&orow[col] = v;
            }
        }
    }
}

// ---------------------------------------------------------------------------
extern "C" void kernel_launch(void* const* d_in, const int* in_sizes, int n_in,
                              void* d_out, int out_size) {
    (void)in_sizes; (void)n_in; (void)out_size;
    const float* x    = (const float*)d_in[0];
    const float* c0   = (const float*)d_in[1];
    const float* c1   = (const float*)d_in[2];
    const float* c2   = (const float*)d_in[3];
    const float* c3   = (const float*)d_in[4];
    const float* bias = (const float*)d_in[5];
    float* out = (float*)d_out;

    cudaFuncSetAttribute(k1, cudaFuncAttributeMaxDynamicSharedMemorySize, 110592);
    cudaFuncSetAttribute(k2, cudaFuncAttributeMaxDynamicSharedMemorySize, 133120);

    k_prep<<<256, 256>>>(c0, c1, c2, c3);
    k_splitXT<<<4096, 256>>>(x);
    k1<<<592, 256, 110592>>>();            // 4 m-chunks x 148, persistent over n
    k2<<<1024, 256, 133120>>>(bias, out);  // 256 output rows per CTA
}

// round 8
// speedup vs baseline: 2.2798x; 1.0806x over previous
#include <cuda_runtime.h>
#include <cuda_bf16.h>
#include <cstdint>
#include <cstddef>

// ============================================================================
// TT-Linear as two merged GEMMs on HMMA (mma.sync bf16, baseline compute_103
// PTX — tcgen05 unavailable in this toolchain target).
//
//   G01[m=(o1,o2,r2)][k=(i1,i2)]  (512x64)
//   G23t[n=(o3,o4)][k2=(r2,i3,i4)] (64x512)
//   stage1: z[b][m=512][i34] = G01 @ x_b^T          (K=64)
//   stage2: y[(b,o12)][o34]  = z_rows @ G23 + bias  (K=512)
//
// bf16 operands stored as interleaved {hi,lo} 32-bit words, split with PRMT.
// 3-term split per GEMM: Ah*Bh + Ah*Bl + Al*Bh.
// R7 change: 16 warps/CTA on both GEMMs (occupancy 12% -> 25%) to feed the
// tensor pipe; k1 CTA tile 128m x 256n.
// ============================================================================

__device__ __align__(16) uint32_t g_A[512 * 64];          // G01 {h,l} words [m][k]
__device__ __align__(16) uint32_t g_B[64 * 512];          // G23t {h,l} words [n][k2]
__device__ __align__(16) uint32_t g_XT[4096u * 4096u];    // x^T {h,l} words [b][i34][i12]
__device__ __align__(16) uint32_t g_Z[134217728u];        // z {h,l} words [b][m][i34]

// ---------------------------------------------------------------- helpers
__device__ __forceinline__ uint32_t prmt(uint32_t a, uint32_t b, uint32_t s) {
    uint32_t d;
    asm("prmt.b32 %0, %1, %2, %3;" : "=r"(d) : "r"(a), "r"(b), "r"(s));
    return d;
}
__device__ __forceinline__ uint32_t pack_hl(float f) {
    __nv_bfloat16 h = __float2bfloat16(f);
    float hf = __bfloat162float(h);
    __nv_bfloat16 l = __float2bfloat16(f - hf);
    return (uint32_t)__bfloat16_as_ushort(h) |
           ((uint32_t)__bfloat16_as_ushort(l) << 16);
}
#define SPLIT_HL(w, H, L) do { H = prmt((w).x, (w).y, 0x5410); \
                               L = prmt((w).x, (w).y, 0x7632); } while (0)

__device__ __forceinline__ void mma16816(float* c, const uint32_t* a,
                                         const uint32_t* b) {
    asm volatile(
        "mma.sync.aligned.m16n8k16.row.col.f32.bf16.bf16.f32 "
        "{%0,%1,%2,%3}, {%4,%5,%6,%7}, {%8,%9}, {%0,%1,%2,%3};"
        : "+f"(c[0]), "+f"(c[1]), "+f"(c[2]), "+f"(c[3])
        : "r"(a[0]), "r"(a[1]), "r"(a[2]), "r"(a[3]), "r"(b[0]), "r"(b[1]));
}
__device__ __forceinline__ void cpa16(uint32_t dst_smem, const void* src) {
    asm volatile("cp.async.cg.shared.global [%0], [%1], 16;"
                 :: "r"(dst_smem), "l"(src) : "memory");
}
__device__ __forceinline__ void cpa_commit() {
    asm volatile("cp.async.commit_group;" ::: "memory");
}
__device__ __forceinline__ void cpa_wait0() {
    asm volatile("cp.async.wait_group 0;" ::: "memory");
}
__device__ __forceinline__ void cpa_wait1() {
    asm volatile("cp.async.wait_group 1;" ::: "memory");
}

// ---------------------------------------------------------------------------
// prep: merge core pairs and split to interleaved bf16 {h,l} words.
// ---------------------------------------------------------------------------
__global__ void k_prep(const float* __restrict__ c0, const float* __restrict__ c1,
                       const float* __restrict__ c2, const float* __restrict__ c3) {
    int t = blockIdx.x * blockDim.x + threadIdx.x;  // 0..65535
    if (t < 32768) {
        int m = t >> 6, k = t & 63;
        int o1 = m >> 6, o2 = (m >> 3) & 7, r2 = m & 7;
        int i1 = k >> 3, i2 = k & 7;
        float s = 0.0f;
#pragma unroll
        for (int r1 = 0; r1 < 8; ++r1)
            s += c0[(i1 * 8 + o1) * 8 + r1] * c1[((r1 * 8 + i2) * 8 + o2) * 8 + r2];
        g_A[t] = pack_hl(s);
    } else {
        int u = t - 32768;
        int n = u >> 9, k2 = u & 511;
        int o3 = n >> 3, o4 = n & 7;
        int r2 = k2 >> 6, i3 = (k2 >> 3) & 7, i4 = k2 & 7;
        float s = 0.0f;
#pragma unroll
        for (int r3 = 0; r3 < 8; ++r3)
            s += c2[((r2 * 8 + i3) * 8 + o3) * 8 + r3] * c3[(r3 * 8 + i4) * 8 + o4];
        g_B[u] = pack_hl(s);
    }
}

// ---------------------------------------------------------------------------
// splitXT: x[b][i12*64+i34] fp32 -> g_XT[b][i34][i12] {h,l} words (transposed).
// ---------------------------------------------------------------------------
__global__ __launch_bounds__(256) void k_splitXT(const float* __restrict__ x) {
    __shared__ float sx[64 * 65];
    const int tid = threadIdx.x;
    const int b = blockIdx.x;
    const float4* src = (const float4*)(x + (size_t)b * 4096);
#pragma unroll
    for (int p = 0; p < 4; ++p) {
        float4 v = src[tid + 256 * p];
        int j = tid + 256 * p;
        int i12 = j >> 4, c = (j & 15) * 4;
        float* d = &sx[i12 * 65 + c];
        d[0] = v.x; d[1] = v.y; d[2] = v.z; d[3] = v.w;
    }
    __syncthreads();
    uint32_t* dst = g_XT + (size_t)b * 4096;
#pragma unroll
    for (int it = 0; it < 16; ++it) {
        int idx = it * 256 + tid;
        int i34 = idx >> 6, i12 = idx & 63;
        dst[idx] = pack_hl(sx[i12 * 65 + i34]);
    }
}

// ---------------------------------------------------------------------------
// k1 (stage 1): z = G01 @ X^T.  512 thr / 16 warps, CTA tile 128m x 256n
// (4 batch rows per iter). Warp grid 2m x 8n, warp tile 64m x 32n.
// SMEM: sA [128][72] + sB double buffer [256][72] x2  (~180 KB).
// Grid 592 = 4 m-chunks x 148 starting n-slots, stride 148 over 1024 chunks.
// ---------------------------------------------------------------------------
__global__ __launch_bounds__(512, 1) void k1() {
    extern __shared__ uint32_t sm1[];
    uint32_t* sA = sm1;                        // 9216 words
    const int tid = threadIdx.x;
    const int lane = tid & 31, w = tid >> 5;   // w 0..15
    const int g = lane >> 2, t4 = lane & 3;
    const int wm = w & 1, wn = w >> 1;         // 2 x 8 warp grid
    const int mc = blockIdx.x & 3;
    const int nc0 = blockIdx.x >> 2;           // 0..147

    // stationary A chunk: g_A rows mc*128..+127 (pitch 64 -> 72)
    {
        const uint4* src = (const uint4*)(g_A + mc * 8192);
        for (int j = tid; j < 2048; j += 512) {
            uint4 v = src[j];
            int row = j >> 4, c4 = (j & 15) << 2;
            *(uint4*)&sA[row * 72 + c4] = v;
        }
    }

    // prologue: async-load first B chunk (256 n-cols x 64 k words) into buf 0
    {
        uint32_t* sB = sm1 + 9216;
        const uint4* src = (const uint4*)(g_XT + (size_t)nc0 * 16384);
        for (int j = tid; j < 4096; j += 512) {
            int row = j >> 4, c4 = (j & 15) << 2;
            cpa16((uint32_t)__cvta_generic_to_shared(&sB[row * 72 + c4]), &src[j]);
        }
        cpa_commit();
    }

    int it = 0;
    for (int nc = nc0; nc < 1024; nc += 148, ++it) {
        uint32_t* sB = sm1 + 9216 + (it & 1) * 18432;
        int ncn = nc + 148;
        if (ncn < 1024) {
            uint32_t* sBn = sm1 + 9216 + ((it + 1) & 1) * 18432;
            const uint4* src = (const uint4*)(g_XT + (size_t)ncn * 16384);
            for (int j = tid; j < 4096; j += 512) {
                int row = j >> 4, c4 = (j & 15) << 2;
                cpa16((uint32_t)__cvta_generic_to_shared(&sBn[row * 72 + c4]), &src[j]);
            }
            cpa_commit();
            cpa_wait1();
        } else {
            cpa_wait0();
        }
        __syncthreads();

        float acc[4][4][4];
#pragma unroll
        for (int a = 0; a < 4; ++a)
#pragma unroll
            for (int b = 0; b < 4; ++b)
#pragma unroll
                for (int q = 0; q < 4; ++q) acc[a][b][q] = 0.0f;

#pragma unroll
        for (int ks = 0; ks < 4; ++ks) {
            const int kA = ks * 16 + t4 * 2;
            uint32_t ah[4][4], al[4][4];
#pragma unroll
            for (int mt = 0; mt < 4; ++mt) {
                int row = wm * 64 + mt * 16 + g;
                uint2 w0 = *(const uint2*)&sA[row * 72 + kA];
                uint2 w1 = *(const uint2*)&sA[(row + 8) * 72 + kA];
                uint2 w2 = *(const uint2*)&sA[row * 72 + kA + 8];
                uint2 w3 = *(const uint2*)&sA[(row + 8) * 72 + kA + 8];
                SPLIT_HL(w0, ah[mt][0], al[mt][0]);
                SPLIT_HL(w1, ah[mt][1], al[mt][1]);
                SPLIT_HL(w2, ah[mt][2], al[mt][2]);
                SPLIT_HL(w3, ah[mt][3], al[mt][3]);
            }
#pragma unroll
            for (int nt = 0; nt < 4; ++nt) {
                int ncol = wn * 32 + nt * 8 + g;
                uint2 u0 = *(const uint2*)&sB[ncol * 72 + kA];
                uint2 u1 = *(const uint2*)&sB[ncol * 72 + kA + 8];
                uint32_t bh[2], bl_[2];
                SPLIT_HL(u0, bh[0], bl_[0]);
                SPLIT_HL(u1, bh[1], bl_[1]);
#pragma unroll
                for (int mt = 0; mt < 4; ++mt) {
                    mma16816(acc[mt][nt], ah[mt], bh);
                    mma16816(acc[mt][nt], ah[mt], bl_);
                    mma16816(acc[mt][nt], al[mt], bh);
                }
            }
        }

        // store z tile: interleaved {h,l} words, STG.64
        const int b0 = nc * 4;
#pragma unroll
        for (int mt = 0; mt < 4; ++mt) {
            int row = mc * 128 + wm * 64 + mt * 16 + g;
#pragma unroll
            for (int nt = 0; nt < 4; ++nt) {
                int ncol = wn * 32 + nt * 8 + t4 * 2;  // 0..255
                int bl2 = ncol >> 6, i34 = ncol & 63;
                size_t base = ((size_t)(b0 + bl2) * 512 + row) * 64 + i34;
                uint2 v0, v1;
                v0.x = pack_hl(acc[mt][nt][0]);
                v0.y = pack_hl(acc[mt][nt][1]);
                v1.x = pack_hl(acc[mt][nt][2]);
                v1.y = pack_hl(acc[mt][nt][3]);
                *(uint2*)&g_Z[base] = v0;
                *(uint2*)&g_Z[base + 8 * 64] = v1;
            }
        }
        __syncthreads();
    }
}

// ---------------------------------------------------------------------------
// k2 (stage 2): y = Z @ G23 + bias. 512 thr / 16 warps, CTA = 512 rows.
// G23 resident in SMEM ([64][520] words); Z streamed into A-frags via LDG.64
// with 1-deep k-prefetch. Grid 512.
// ---------------------------------------------------------------------------
__global__ __launch_bounds__(512, 1) void k2(const float* __restrict__ bias,
                                             float* __restrict__ out) {
    extern __shared__ uint32_t sm2[];   // sB [64][520] = 33280 words
    uint32_t* sB = sm2;
    const int tid = threadIdx.x;
    const int lane = tid & 31, w = tid >> 5;   // w 0..15
    const int g = lane >> 2, t4 = lane & 3;

    {
        const uint4* src = (const uint4*)g_B;
        for (int j = tid; j < 8192; j += 512) {
            uint4 v = src[j];
            int row = j >> 7, c4 = (j & 127) << 2;
            *(uint4*)&sB[row * 520 + c4] = v;
        }
    }

    const uint32_t* p0[2];
    const uint32_t* p8[2];
#pragma unroll
    for (int mt = 0; mt < 2; ++mt) {
        size_t gr = (size_t)blockIdx.x * 512 + w * 32 + mt * 16 + g;
        p0[mt] = g_Z + gr * 512;
        p8[mt] = g_Z + (gr + 8) * 512;
    }

    float acc[2][8][4];
#pragma unroll
    for (int a = 0; a < 2; ++a)
#pragma unroll
        for (int b = 0; b < 8; ++b)
#pragma unroll
            for (int q = 0; q < 4; ++q) acc[a][b][q] = 0.0f;

    uint2 aw[2][2][4];
    {
        const int kA = t4 * 2;
#pragma unroll
        for (int mt = 0; mt < 2; ++mt) {
            aw[0][mt][0] = *(const uint2*)(p0[mt] + kA);
            aw[0][mt][1] = *(const uint2*)(p8[mt] + kA);
            aw[0][mt][2] = *(const uint2*)(p0[mt] + kA + 8);
            aw[0][mt][3] = *(const uint2*)(p8[mt] + kA + 8);
        }
    }
    __syncthreads();

    for (int ks = 0; ks < 32; ++ks) {
        const int cur = ks & 1;
        if (ks < 31) {
            const int kA = (ks + 1) * 16 + t4 * 2;
#pragma unroll
            for (int mt = 0; mt < 2; ++mt) {
                aw[cur ^ 1][mt][0] = *(const uint2*)(p0[mt] + kA);
                aw[cur ^ 1][mt][1] = *(const uint2*)(p8[mt] + kA);
                aw[cur ^ 1][mt][2] = *(const uint2*)(p0[mt] + kA + 8);
                aw[cur ^ 1][mt][3] = *(const uint2*)(p8[mt] + kA + 8);
            }
        }
        uint32_t ah[2][4], al[2][4];
#pragma unroll
        for (int mt = 0; mt < 2; ++mt) {
            SPLIT_HL(aw[cur][mt][0], ah[mt][0], al[mt][0]);
            SPLIT_HL(aw[cur][mt][1], ah[mt][1], al[mt][1]);
            SPLIT_HL(aw[cur][mt][2], ah[mt][2], al[mt][2]);
            SPLIT_HL(aw[cur][mt][3], ah[mt][3], al[mt][3]);
        }
        const int kB = ks * 16 + t4 * 2;
#pragma unroll
        for (int nt = 0; nt < 8; ++nt) {
            int ncol = nt * 8 + g;
            uint2 u0 = *(const uint2*)&sB[ncol * 520 + kB];
            uint2 u1 = *(const uint2*)&sB[ncol * 520 + kB + 8];
            uint32_t bh[2], bl_[2];
            SPLIT_HL(u0, bh[0], bl_[0]);
            SPLIT_HL(u1, bh[1], bl_[1]);
#pragma unroll
            for (int mt = 0; mt < 2; ++mt) {
                mma16816(acc[mt][nt], ah[mt], bh);
                mma16816(acc[mt][nt], ah[mt], bl_);
                mma16816(acc[mt][nt], al[mt], bh);
            }
        }
    }

    // epilogue: +bias, store
#pragma unroll
    for (int mt = 0; mt < 2; ++mt) {
        size_t grow0 = (size_t)blockIdx.x * 512 + w * 32 + mt * 16 + g;
#pragma unroll
        for (int half = 0; half < 2; ++half) {
            size_t grow = grow0 + half * 8;
            int o12 = (int)(grow & 63);
            float* orow = out + grow * 64;
            const int ci = half * 2;
#pragma unroll
            for (int nt = 0; nt < 8; ++nt) {
                int col = nt * 8 + t4 * 2;
                float2 bv = __ldg((const float2*)&bias[o12 * 64 + col]);
                float2 v;
                v.x = acc[mt][nt][ci] + bv.x;
                v.y = acc[mt][nt][ci + 1] + bv.y;
                *(float2*)&orow[col] = v;
            }
        }
    }
}

// ---------------------------------------------------------------------------
extern "C" void kernel_launch(void* const* d_in, const int* in_sizes, int n_in,
                              void* d_out, int out_size) {
    (void)in_sizes; (void)n_in; (void)out_size;
    const float* x    = (const float*)d_in[0];
    const float* c0   = (const float*)d_in[1];
    const float* c1   = (const float*)d_in[2];
    const float* c2   = (const float*)d_in[3];
    const float* c3   = (const float*)d_in[4];
    const float* bias = (const float*)d_in[5];
    float* out = (float*)d_out;

    cudaFuncSetAttribute(k1, cudaFuncAttributeMaxDynamicSharedMemorySize, 184320);
    cudaFuncSetAttribute(k2, cudaFuncAttributeMaxDynamicSharedMemorySize, 133120);

    k_prep<<<256, 256>>>(c0, c1, c2, c3);
    k_splitXT<<<4096, 256>>>(x);
    k1<<<592, 512, 184320>>>();            // 16 warps, 128m x 256n tiles
    k2<<<512, 512, 133120>>>(bias, out);   // 16 warps, 512 rows per CTA
}